// round 6
// baseline (speedup 1.0000x reference)
#include <cuda_runtime.h>
#include <math.h>

// Problem constants
// B=8, L=1024, E=896, H=4, DK=2048, DV=768, TOP_K=64

__device__ float g_qp[67108864];   // 8192*8192 q_proj (pre-divided by sqrt(DK))
__device__ float g_kp[67108864];   // 8192*8192 k_proj
__device__ float g_vp[25165824];   // 8192*3072 v_proj
__device__ float g_mix[25165824];  // [B, L, H, DV] = 8192*3072
__device__ float g_attn[33554432]; // fallback attn scratch

// ---------------------------------------------------------------------------
// NT GEMM: C[M,N] = A(MxK) * B(NxK)^T, 128x128 tile, BK=16, 256 thr, 8x8/thr.
// Per-output accumulation is a SINGLE sequential ascending-k fma chain —
// deliberately matching the per-element accumulation order of cuBLAS SGEMM /
// Eigen gebp so the score-path roundings correlate with the reference's
// (top-k keep-set is discontinuous in the scores; matching rounding order is
// the only way to agree on the boundary elements).
// Epilogue: if divisor != 1: C = __fdiv_rn(acc, divisor)  (emulates
// jnp's q_proj / sqrt(DK) elementwise fp32 division), else C = alpha*acc.
// ---------------------------------------------------------------------------
__global__ __launch_bounds__(256) void gemm_nt(
    const float* __restrict__ A, const float* __restrict__ B, float* __restrict__ C,
    int K, int lda, int ldb, int ldc, int hdiv,
    long long sa1, long long sa2, long long sb1, long long sb2,
    long long sc1, long long sc2, float alpha, float divisor)
{
    __shared__ float As[16][128];
    __shared__ float Bs[16][128];

    const int z = blockIdx.z;
    const long long zb = z / hdiv, zh = z % hdiv;
    A += zb * sa1 + zh * sa2;
    B += zb * sb1 + zh * sb2;
    C += zb * sc1 + zh * sc2;

    const int tid = threadIdx.x;
    const long long bm = (long long)blockIdx.y * 128;
    const long long bn = (long long)blockIdx.x * 128;

    const int lr = tid >> 2;          // 0..63
    const int lk = (tid & 3) << 2;    // 0,4,8,12
    const int ty = tid >> 4;          // 0..15
    const int tx = tid & 15;          // 0..15

    float acc[8][8];
#pragma unroll
    for (int i = 0; i < 8; i++)
#pragma unroll
        for (int j = 0; j < 8; j++) acc[i][j] = 0.f;

    const float* Ap0 = A + (bm + lr) * lda + lk;
    const float* Ap1 = A + (bm + lr + 64) * lda + lk;
    const float* Bp0 = B + (bn + lr) * ldb + lk;
    const float* Bp1 = B + (bn + lr + 64) * ldb + lk;

    for (int k0 = 0; k0 < K; k0 += 16) {
        float4 a0 = *(const float4*)(Ap0 + k0);
        float4 a1 = *(const float4*)(Ap1 + k0);
        float4 b0 = *(const float4*)(Bp0 + k0);
        float4 b1 = *(const float4*)(Bp1 + k0);
        As[lk + 0][lr] = a0.x; As[lk + 1][lr] = a0.y; As[lk + 2][lr] = a0.z; As[lk + 3][lr] = a0.w;
        As[lk + 0][lr + 64] = a1.x; As[lk + 1][lr + 64] = a1.y; As[lk + 2][lr + 64] = a1.z; As[lk + 3][lr + 64] = a1.w;
        Bs[lk + 0][lr] = b0.x; Bs[lk + 1][lr] = b0.y; Bs[lk + 2][lr] = b0.z; Bs[lk + 3][lr] = b0.w;
        Bs[lk + 0][lr + 64] = b1.x; Bs[lk + 1][lr + 64] = b1.y; Bs[lk + 2][lr + 64] = b1.z; Bs[lk + 3][lr + 64] = b1.w;
        __syncthreads();
#pragma unroll
        for (int kk = 0; kk < 16; kk++) {
            float4 t0 = *(const float4*)(&As[kk][ty * 8]);
            float4 t1 = *(const float4*)(&As[kk][ty * 8 + 4]);
            float4 u0 = *(const float4*)(&Bs[kk][tx * 8]);
            float4 u1 = *(const float4*)(&Bs[kk][tx * 8 + 4]);
            float av[8] = {t0.x, t0.y, t0.z, t0.w, t1.x, t1.y, t1.z, t1.w};
            float bv[8] = {u0.x, u0.y, u0.z, u0.w, u1.x, u1.y, u1.z, u1.w};
#pragma unroll
            for (int i = 0; i < 8; i++)
#pragma unroll
                for (int j = 0; j < 8; j++)
                    acc[i][j] = fmaf(av[i], bv[j], acc[i][j]);
        }
        __syncthreads();
    }

    const bool dodiv = (divisor != 1.0f);
#pragma unroll
    for (int i = 0; i < 8; i++) {
        float* Cr = C + (bm + ty * 8 + i) * ldc + bn + tx * 8;
        float o[8];
#pragma unroll
        for (int j = 0; j < 8; j++)
            o[j] = dodiv ? __fdiv_rn(acc[i][j], divisor) : alpha * acc[i][j];
        *(float4*)(Cr) = make_float4(o[0], o[1], o[2], o[3]);
        *(float4*)(Cr + 4) = make_float4(o[4], o[5], o[6], o[7]);
    }
}

// ---------------------------------------------------------------------------
// NN GEMM: C[M,N] = A(MxK) * B(KxN)   (attn @ Vproj) — smooth error path.
// ---------------------------------------------------------------------------
__global__ __launch_bounds__(256) void gemm_nn(
    const float* __restrict__ A, const float* __restrict__ B, float* __restrict__ C,
    int K, int lda, int ldb, int ldc, int hdiv,
    long long sa1, long long sa2, long long sb1, long long sb2,
    long long sc1, long long sc2, float alpha)
{
    __shared__ float As[16][128];
    __shared__ float Bs[16][128];

    const int z = blockIdx.z;
    const long long zb = z / hdiv, zh = z % hdiv;
    A += zb * sa1 + zh * sa2;
    B += zb * sb1 + zh * sb2;
    C += zb * sc1 + zh * sc2;

    const int tid = threadIdx.x;
    const long long bm = (long long)blockIdx.y * 128;
    const long long bn = (long long)blockIdx.x * 128;

    const int lr = tid >> 2;
    const int lk = (tid & 3) << 2;
    const int bkr = tid >> 5;
    const int bn4 = (tid & 31) << 2;
    const int ty = tid >> 4;
    const int tx = tid & 15;

    float acc[8][8];
#pragma unroll
    for (int i = 0; i < 8; i++)
#pragma unroll
        for (int j = 0; j < 8; j++) acc[i][j] = 0.f;

    const float* Ap0 = A + (bm + lr) * lda + lk;
    const float* Ap1 = A + (bm + lr + 64) * lda + lk;
    const float* Bp0 = B + (long long)bkr * ldb + bn + bn4;
    const float* Bp1 = B + (long long)(bkr + 8) * ldb + bn + bn4;

    for (int k0 = 0; k0 < K; k0 += 16) {
        float4 a0 = *(const float4*)(Ap0 + k0);
        float4 a1 = *(const float4*)(Ap1 + k0);
        float4 b0 = *(const float4*)(Bp0 + (long long)k0 * ldb);
        float4 b1 = *(const float4*)(Bp1 + (long long)k0 * ldb);
        As[lk + 0][lr] = a0.x; As[lk + 1][lr] = a0.y; As[lk + 2][lr] = a0.z; As[lk + 3][lr] = a0.w;
        As[lk + 0][lr + 64] = a1.x; As[lk + 1][lr + 64] = a1.y; As[lk + 2][lr + 64] = a1.z; As[lk + 3][lr + 64] = a1.w;
        *(float4*)(&Bs[bkr][bn4]) = b0;
        *(float4*)(&Bs[bkr + 8][bn4]) = b1;
        __syncthreads();
#pragma unroll
        for (int kk = 0; kk < 16; kk++) {
            float4 t0 = *(const float4*)(&As[kk][ty * 8]);
            float4 t1 = *(const float4*)(&As[kk][ty * 8 + 4]);
            float4 u0 = *(const float4*)(&Bs[kk][tx * 8]);
            float4 u1 = *(const float4*)(&Bs[kk][tx * 8 + 4]);
            float av[8] = {t0.x, t0.y, t0.z, t0.w, t1.x, t1.y, t1.z, t1.w};
            float bv[8] = {u0.x, u0.y, u0.z, u0.w, u1.x, u1.y, u1.z, u1.w};
#pragma unroll
            for (int i = 0; i < 8; i++)
#pragma unroll
                for (int j = 0; j < 8; j++)
                    acc[i][j] = fmaf(av[i], bv[j], acc[i][j]);
        }
        __syncthreads();
    }

#pragma unroll
    for (int i = 0; i < 8; i++) {
        float* Cr = C + (bm + ty * 8 + i) * ldc + bn + tx * 8;
        float4 c0 = make_float4(alpha * acc[i][0], alpha * acc[i][1], alpha * acc[i][2], alpha * acc[i][3]);
        float4 c1 = make_float4(alpha * acc[i][4], alpha * acc[i][5], alpha * acc[i][6], alpha * acc[i][7]);
        *(float4*)(Cr) = c0;
        *(float4*)(Cr + 4) = c1;
    }
}

// ---------------------------------------------------------------------------
// Exact top-64 (torch/jax topk semantics incl. first-index tie break) + softmax
// ---------------------------------------------------------------------------
__global__ __launch_bounds__(256) void topk_softmax_kernel(
    float* __restrict__ attn, const float* __restrict__ qmask)
{
    __shared__ unsigned keys[1024];
    __shared__ float vals[1024];
    __shared__ unsigned hist[256];
    __shared__ float red[256];
    __shared__ unsigned char keepEq[1024];
    __shared__ unsigned sh_prefix, sh_krem, sh_e;

    const int tid = threadIdx.x;
    const int row = blockIdx.x;             // (b*H + h)*L + lq
    float* a = attn + (long long)row * 1024;
    const int b = row >> 12;                // H*L = 4096
    const int lq = row & 1023;
    const float mk = qmask[(b << 10) + lq];
    const bool dense = (mk <= 0.5f);

#pragma unroll
    for (int i = 0; i < 4; i++) {
        int idx = tid + (i << 8);
        float x = a[idx];
        vals[idx] = x;
        unsigned u = __float_as_uint(x);
        keys[idx] = (u & 0x80000000u) ? ~u : (u | 0x80000000u);
    }
    __syncthreads();

    unsigned thr = 0;
    int r = 0;
    bool tie = false;
    if (!dense) {
        unsigned prefix = 0;
        int krem = 64;
        for (int pass = 0; pass < 4; pass++) {
            const int shift = 24 - (pass << 3);
            hist[tid] = 0;
            __syncthreads();
            const unsigned pmask = (pass == 0) ? 0u : (0xFFFFFFFFu << (shift + 8));
#pragma unroll
            for (int i = 0; i < 4; i++) {
                unsigned kk = keys[tid + (i << 8)];
                if ((kk & pmask) == prefix)
                    atomicAdd(&hist[(kk >> shift) & 255u], 1u);
            }
            __syncthreads();
            if (tid == 0) {
                int cum = 0, bsel = 0;
                for (int bb = 255; bb >= 0; bb--) {
                    int c = (int)hist[bb];
                    if (cum + c >= krem) { bsel = bb; break; }
                    cum += c;
                }
                sh_prefix = prefix | ((unsigned)bsel << shift);
                sh_krem = (unsigned)(krem - cum);
            }
            __syncthreads();
            prefix = sh_prefix;
            krem = (int)sh_krem;
        }
        thr = prefix;
        r = krem;
        if (tid == 0) sh_e = 0;
        __syncthreads();
        unsigned le = 0;
#pragma unroll
        for (int i = 0; i < 4; i++) le += (keys[tid + (i << 8)] == thr) ? 1u : 0u;
        if (le) atomicAdd(&sh_e, le);
        __syncthreads();
        tie = ((int)sh_e != r);
        if (tie) {
            if (tid == 0) {
                int cnt = 0;
                for (int i2 = 0; i2 < 1024; i2++) {
                    unsigned char kp = 0;
                    if (keys[i2] == thr) { if (cnt < r) kp = 1; cnt++; }
                    keepEq[i2] = kp;
                }
            }
            __syncthreads();
        }
    }

    float lmax = -3.402823466e38f;
#pragma unroll
    for (int i = 0; i < 4; i++) lmax = fmaxf(lmax, vals[tid + (i << 8)]);
    red[tid] = lmax;
    __syncthreads();
    for (int s = 128; s > 0; s >>= 1) {
        if (tid < s) red[tid] = fmaxf(red[tid], red[tid + s]);
        __syncthreads();
    }
    const float m = red[0];
    __syncthreads();

    float ev[4];
    float lsum = 0.f;
#pragma unroll
    for (int i = 0; i < 4; i++) {
        int idx = tid + (i << 8);
        unsigned kk = keys[idx];
        bool keep = dense || (kk > thr) || (kk == thr && (!tie || keepEq[idx]));
        float e = keep ? expf(vals[idx] - m) : 0.f;
        ev[i] = e;
        lsum += e;
    }
    red[tid] = lsum;
    __syncthreads();
    for (int s = 128; s > 0; s >>= 1) {
        if (tid < s) red[tid] += red[tid + s];
        __syncthreads();
    }
    const float inv = 1.f / red[0];
#pragma unroll
    for (int i = 0; i < 4; i++) a[tid + (i << 8)] = ev[i] * inv;
}

// ---------------------------------------------------------------------------
extern "C" void kernel_launch(void* const* d_in, const int* in_sizes, int n_in,
                              void* d_out, int out_size)
{
    const float* q     = (const float*)d_in[0];
    const float* k     = (const float*)d_in[1];
    const float* v     = (const float*)d_in[2];
    const float* qmask = (const float*)d_in[3];
    const float* w_qs  = (const float*)d_in[4];
    const float* w_ks  = (const float*)d_in[5];
    const float* w_vs  = (const float*)d_in[6];
    const float* fc_w  = (const float*)d_in[7];
    float* outP = (float*)d_out;

    float *qp, *kp, *vp, *mix, *attnScratch;
    cudaGetSymbolAddress((void**)&qp,  g_qp);
    cudaGetSymbolAddress((void**)&kp,  g_kp);
    cudaGetSymbolAddress((void**)&vp,  g_vp);
    cudaGetSymbolAddress((void**)&mix, g_mix);
    cudaGetSymbolAddress((void**)&attnScratch, g_attn);

    const long long outElems  = 8LL * 1024 * 768;
    const long long attnElems = 8LL * 4 * 1024 * 1024;
    float* attnP = ((long long)out_size >= outElems + attnElems) ? (outP + outElems)
                                                                 : attnScratch;

    const float scaleDiv = 45.254834f;  // float32(sqrt(2048)), matches jnp q_proj/scale

    // q_proj: sequential ascending-e chain, then IEEE-divide by sqrt(DK)
    gemm_nt<<<dim3(64, 64, 1), dim3(256)>>>(q, w_qs, qp, 896, 896, 896, 8192,
                                            1, 0, 0, 0, 0, 0, 0, 1.f, scaleDiv);
    // k_proj: sequential chain, no scale
    gemm_nt<<<dim3(64, 64, 1), dim3(256)>>>(k, w_ks, kp, 896, 896, 896, 8192,
                                            1, 0, 0, 0, 0, 0, 0, 1.f, 1.f);
    // v_proj
    gemm_nt<<<dim3(24, 64, 1), dim3(256)>>>(v, w_vs, vp, 768, 768, 768, 3072,
                                            1, 0, 0, 0, 0, 0, 0, 1.f, 1.f);

    // attn scores: per (b,h) [1024,1024] = (Q/sqrt(DK)) @ K^T, sequential chain
    gemm_nt<<<dim3(8, 8, 32), dim3(256)>>>(qp, kp, attnP, 2048, 8192, 8192, 1024,
                                           4,
                                           1024LL * 8192, 2048,
                                           1024LL * 8192, 2048,
                                           4LL * 1024 * 1024, 1024LL * 1024,
                                           1.f, 1.f);

    // exact top-64 + softmax, in place
    topk_softmax_kernel<<<32768, 256>>>(attnP, qmask);

    // mixed: per (b,h) [1024,768] = attn @ Vproj ; stored as [B, L, H, DV]
    gemm_nn<<<dim3(6, 8, 32), dim3(256)>>>(attnP, vp, mix, 1024, 1024, 3072, 3072,
                                           4,
                                           4LL * 1024 * 1024, 1024LL * 1024,
                                           1024LL * 3072, 768,
                                           1024LL * 3072, 768,
                                           1.f);

    // out: [8192,768] = mixed[8192,3072] @ fc_w[768,3072]^T
    gemm_nt<<<dim3(6, 64, 1), dim3(256)>>>(mix, fc_w, outP, 3072, 3072, 3072, 768,
                                           1, 0, 0, 0, 0, 0, 0, 1.f, 1.f);
}

// round 7
// speedup vs baseline: 1.0379x; 1.0379x over previous
#include <cuda_runtime.h>
#include <math.h>

// Problem constants
// B=8, L=1024, E=896, H=4, DK=2048, DV=768, TOP_K=64

__device__ float g_qp[67108864];   // 8192*8192 q_proj (pre-divided by sqrt(DK))
__device__ float g_kp[67108864];   // 8192*8192 k_proj
__device__ float g_vp[25165824];   // 8192*3072 v_proj
__device__ float g_mix[25165824];  // [B, L, H, DV] = 8192*3072
__device__ float g_attn[33554432]; // fallback attn scratch

// ---------------------------------------------------------------------------
// NT GEMM: C[M,N] = A(MxK) * B(NxK)^T, 128x128 tile, BK=16, 256 thr, 8x8/thr.
// Double-buffered smem + register prefetch: LDG for block k+1 issued before
// computing block k, stored to the alternate buffer after compute, ONE
// __syncthreads per iteration. Per-output accumulation remains a SINGLE
// sequential ascending-k fma chain (bit-identical to the reference's
// cuBLAS-style accumulation; the top-k keep-set depends on it).
// Epilogue: divisor!=1 -> C = __fdiv_rn(acc, divisor) (emulates q_proj/scale),
// else C = alpha*acc.
// ---------------------------------------------------------------------------
__global__ __launch_bounds__(256) void gemm_nt(
    const float* __restrict__ A, const float* __restrict__ B, float* __restrict__ C,
    int K, int lda, int ldb, int ldc, int hdiv,
    long long sa1, long long sa2, long long sb1, long long sb2,
    long long sc1, long long sc2, float alpha, float divisor)
{
    __shared__ float As[2][16][128];
    __shared__ float Bs[2][16][128];

    const int z = blockIdx.z;
    const long long zb = z / hdiv, zh = z % hdiv;
    A += zb * sa1 + zh * sa2;
    B += zb * sb1 + zh * sb2;
    C += zb * sc1 + zh * sc2;

    const int tid = threadIdx.x;
    const long long bm = (long long)blockIdx.y * 128;
    const long long bn = (long long)blockIdx.x * 128;

    const int lr = tid >> 2;          // 0..63
    const int lk = (tid & 3) << 2;    // 0,4,8,12
    const int ty = tid >> 4;          // 0..15
    const int tx = tid & 15;          // 0..15

    float acc[8][8];
#pragma unroll
    for (int i = 0; i < 8; i++)
#pragma unroll
        for (int j = 0; j < 8; j++) acc[i][j] = 0.f;

    const float* Ap0 = A + (bm + lr) * lda + lk;
    const float* Ap1 = A + (bm + lr + 64) * lda + lk;
    const float* Bp0 = B + (bn + lr) * ldb + lk;
    const float* Bp1 = B + (bn + lr + 64) * ldb + lk;

    // prologue: load block 0 into buffer 0
    {
        float4 a0 = *(const float4*)(Ap0);
        float4 a1 = *(const float4*)(Ap1);
        float4 b0 = *(const float4*)(Bp0);
        float4 b1 = *(const float4*)(Bp1);
        As[0][lk + 0][lr] = a0.x; As[0][lk + 1][lr] = a0.y; As[0][lk + 2][lr] = a0.z; As[0][lk + 3][lr] = a0.w;
        As[0][lk + 0][lr + 64] = a1.x; As[0][lk + 1][lr + 64] = a1.y; As[0][lk + 2][lr + 64] = a1.z; As[0][lk + 3][lr + 64] = a1.w;
        Bs[0][lk + 0][lr] = b0.x; Bs[0][lk + 1][lr] = b0.y; Bs[0][lk + 2][lr] = b0.z; Bs[0][lk + 3][lr] = b0.w;
        Bs[0][lk + 0][lr + 64] = b1.x; Bs[0][lk + 1][lr + 64] = b1.y; Bs[0][lk + 2][lr + 64] = b1.z; Bs[0][lk + 3][lr + 64] = b1.w;
    }
    __syncthreads();

    int buf = 0;
    for (int k0 = 0; k0 < K; k0 += 16) {
        const bool has_next = (k0 + 16 < K);
        float4 na0, na1, nb0, nb1;
        if (has_next) {
            na0 = *(const float4*)(Ap0 + k0 + 16);
            na1 = *(const float4*)(Ap1 + k0 + 16);
            nb0 = *(const float4*)(Bp0 + k0 + 16);
            nb1 = *(const float4*)(Bp1 + k0 + 16);
        }

#pragma unroll
        for (int kk = 0; kk < 16; kk++) {
            float4 t0 = *(const float4*)(&As[buf][kk][ty * 8]);
            float4 t1 = *(const float4*)(&As[buf][kk][ty * 8 + 4]);
            float4 u0 = *(const float4*)(&Bs[buf][kk][tx * 8]);
            float4 u1 = *(const float4*)(&Bs[buf][kk][tx * 8 + 4]);
            float av[8] = {t0.x, t0.y, t0.z, t0.w, t1.x, t1.y, t1.z, t1.w};
            float bv[8] = {u0.x, u0.y, u0.z, u0.w, u1.x, u1.y, u1.z, u1.w};
#pragma unroll
            for (int i = 0; i < 8; i++)
#pragma unroll
                for (int j = 0; j < 8; j++)
                    acc[i][j] = fmaf(av[i], bv[j], acc[i][j]);
        }

        if (has_next) {
            const int nb = buf ^ 1;
            As[nb][lk + 0][lr] = na0.x; As[nb][lk + 1][lr] = na0.y; As[nb][lk + 2][lr] = na0.z; As[nb][lk + 3][lr] = na0.w;
            As[nb][lk + 0][lr + 64] = na1.x; As[nb][lk + 1][lr + 64] = na1.y; As[nb][lk + 2][lr + 64] = na1.z; As[nb][lk + 3][lr + 64] = na1.w;
            Bs[nb][lk + 0][lr] = nb0.x; Bs[nb][lk + 1][lr] = nb0.y; Bs[nb][lk + 2][lr] = nb0.z; Bs[nb][lk + 3][lr] = nb0.w;
            Bs[nb][lk + 0][lr + 64] = nb1.x; Bs[nb][lk + 1][lr + 64] = nb1.y; Bs[nb][lk + 2][lr + 64] = nb1.z; Bs[nb][lk + 3][lr + 64] = nb1.w;
        }
        __syncthreads();
        buf ^= 1;
    }

    const bool dodiv = (divisor != 1.0f);
#pragma unroll
    for (int i = 0; i < 8; i++) {
        float* Cr = C + (bm + ty * 8 + i) * ldc + bn + tx * 8;
        float o[8];
#pragma unroll
        for (int j = 0; j < 8; j++)
            o[j] = dodiv ? __fdiv_rn(acc[i][j], divisor) : alpha * acc[i][j];
        *(float4*)(Cr) = make_float4(o[0], o[1], o[2], o[3]);
        *(float4*)(Cr + 4) = make_float4(o[4], o[5], o[6], o[7]);
    }
}

// ---------------------------------------------------------------------------
// NN GEMM: C[M,N] = A(MxK) * B(KxN)  (attn @ Vproj) — same pipelined scheme.
// ---------------------------------------------------------------------------
__global__ __launch_bounds__(256) void gemm_nn(
    const float* __restrict__ A, const float* __restrict__ B, float* __restrict__ C,
    int K, int lda, int ldb, int ldc, int hdiv,
    long long sa1, long long sa2, long long sb1, long long sb2,
    long long sc1, long long sc2, float alpha)
{
    __shared__ float As[2][16][128];
    __shared__ float Bs[2][16][128];

    const int z = blockIdx.z;
    const long long zb = z / hdiv, zh = z % hdiv;
    A += zb * sa1 + zh * sa2;
    B += zb * sb1 + zh * sb2;
    C += zb * sc1 + zh * sc2;

    const int tid = threadIdx.x;
    const long long bm = (long long)blockIdx.y * 128;
    const long long bn = (long long)blockIdx.x * 128;

    const int lr = tid >> 2;
    const int lk = (tid & 3) << 2;
    const int bkr = tid >> 5;         // 0..7
    const int bn4 = (tid & 31) << 2;  // 0..124
    const int ty = tid >> 4;
    const int tx = tid & 15;

    float acc[8][8];
#pragma unroll
    for (int i = 0; i < 8; i++)
#pragma unroll
        for (int j = 0; j < 8; j++) acc[i][j] = 0.f;

    const float* Ap0 = A + (bm + lr) * lda + lk;
    const float* Ap1 = A + (bm + lr + 64) * lda + lk;
    const float* Bp0 = B + (long long)bkr * ldb + bn + bn4;
    const float* Bp1 = B + (long long)(bkr + 8) * ldb + bn + bn4;

    {
        float4 a0 = *(const float4*)(Ap0);
        float4 a1 = *(const float4*)(Ap1);
        float4 b0 = *(const float4*)(Bp0);
        float4 b1 = *(const float4*)(Bp1);
        As[0][lk + 0][lr] = a0.x; As[0][lk + 1][lr] = a0.y; As[0][lk + 2][lr] = a0.z; As[0][lk + 3][lr] = a0.w;
        As[0][lk + 0][lr + 64] = a1.x; As[0][lk + 1][lr + 64] = a1.y; As[0][lk + 2][lr + 64] = a1.z; As[0][lk + 3][lr + 64] = a1.w;
        *(float4*)(&Bs[0][bkr][bn4]) = b0;
        *(float4*)(&Bs[0][bkr + 8][bn4]) = b1;
    }
    __syncthreads();

    int buf = 0;
    for (int k0 = 0; k0 < K; k0 += 16) {
        const bool has_next = (k0 + 16 < K);
        float4 na0, na1, nb0, nb1;
        if (has_next) {
            na0 = *(const float4*)(Ap0 + k0 + 16);
            na1 = *(const float4*)(Ap1 + k0 + 16);
            nb0 = *(const float4*)(Bp0 + (long long)(k0 + 16) * ldb);
            nb1 = *(const float4*)(Bp1 + (long long)(k0 + 16) * ldb);
        }

#pragma unroll
        for (int kk = 0; kk < 16; kk++) {
            float4 t0 = *(const float4*)(&As[buf][kk][ty * 8]);
            float4 t1 = *(const float4*)(&As[buf][kk][ty * 8 + 4]);
            float4 u0 = *(const float4*)(&Bs[buf][kk][tx * 8]);
            float4 u1 = *(const float4*)(&Bs[buf][kk][tx * 8 + 4]);
            float av[8] = {t0.x, t0.y, t0.z, t0.w, t1.x, t1.y, t1.z, t1.w};
            float bv[8] = {u0.x, u0.y, u0.z, u0.w, u1.x, u1.y, u1.z, u1.w};
#pragma unroll
            for (int i = 0; i < 8; i++)
#pragma unroll
                for (int j = 0; j < 8; j++)
                    acc[i][j] = fmaf(av[i], bv[j], acc[i][j]);
        }

        if (has_next) {
            const int nb = buf ^ 1;
            As[nb][lk + 0][lr] = na0.x; As[nb][lk + 1][lr] = na0.y; As[nb][lk + 2][lr] = na0.z; As[nb][lk + 3][lr] = na0.w;
            As[nb][lk + 0][lr + 64] = na1.x; As[nb][lk + 1][lr + 64] = na1.y; As[nb][lk + 2][lr + 64] = na1.z; As[nb][lk + 3][lr + 64] = na1.w;
            *(float4*)(&Bs[nb][bkr][bn4]) = nb0;
            *(float4*)(&Bs[nb][bkr + 8][bn4]) = nb1;
        }
        __syncthreads();
        buf ^= 1;
    }

#pragma unroll
    for (int i = 0; i < 8; i++) {
        float* Cr = C + (bm + ty * 8 + i) * ldc + bn + tx * 8;
        float4 c0 = make_float4(alpha * acc[i][0], alpha * acc[i][1], alpha * acc[i][2], alpha * acc[i][3]);
        float4 c1 = make_float4(alpha * acc[i][4], alpha * acc[i][5], alpha * acc[i][6], alpha * acc[i][7]);
        *(float4*)(Cr) = c0;
        *(float4*)(Cr + 4) = c1;
    }
}

// ---------------------------------------------------------------------------
// Exact top-64 (torch/jax topk semantics incl. first-index tie break) + softmax
// ---------------------------------------------------------------------------
__global__ __launch_bounds__(256) void topk_softmax_kernel(
    float* __restrict__ attn, const float* __restrict__ qmask)
{
    __shared__ unsigned keys[1024];
    __shared__ float vals[1024];
    __shared__ unsigned hist[256];
    __shared__ float red[256];
    __shared__ unsigned char keepEq[1024];
    __shared__ unsigned sh_prefix, sh_krem, sh_e;

    const int tid = threadIdx.x;
    const int row = blockIdx.x;             // (b*H + h)*L + lq
    float* a = attn + (long long)row * 1024;
    const int b = row >> 12;                // H*L = 4096
    const int lq = row & 1023;
    const float mk = qmask[(b << 10) + lq];
    const bool dense = (mk <= 0.5f);

#pragma unroll
    for (int i = 0; i < 4; i++) {
        int idx = tid + (i << 8);
        float x = a[idx];
        vals[idx] = x;
        unsigned u = __float_as_uint(x);
        keys[idx] = (u & 0x80000000u) ? ~u : (u | 0x80000000u);
    }
    __syncthreads();

    unsigned thr = 0;
    int r = 0;
    bool tie = false;
    if (!dense) {
        unsigned prefix = 0;
        int krem = 64;
        for (int pass = 0; pass < 4; pass++) {
            const int shift = 24 - (pass << 3);
            hist[tid] = 0;
            __syncthreads();
            const unsigned pmask = (pass == 0) ? 0u : (0xFFFFFFFFu << (shift + 8));
#pragma unroll
            for (int i = 0; i < 4; i++) {
                unsigned kk = keys[tid + (i << 8)];
                if ((kk & pmask) == prefix)
                    atomicAdd(&hist[(kk >> shift) & 255u], 1u);
            }
            __syncthreads();
            if (tid == 0) {
                int cum = 0, bsel = 0;
                for (int bb = 255; bb >= 0; bb--) {
                    int c = (int)hist[bb];
                    if (cum + c >= krem) { bsel = bb; break; }
                    cum += c;
                }
                sh_prefix = prefix | ((unsigned)bsel << shift);
                sh_krem = (unsigned)(krem - cum);
            }
            __syncthreads();
            prefix = sh_prefix;
            krem = (int)sh_krem;
        }
        thr = prefix;
        r = krem;
        if (tid == 0) sh_e = 0;
        __syncthreads();
        unsigned le = 0;
#pragma unroll
        for (int i = 0; i < 4; i++) le += (keys[tid + (i << 8)] == thr) ? 1u : 0u;
        if (le) atomicAdd(&sh_e, le);
        __syncthreads();
        tie = ((int)sh_e != r);
        if (tie) {
            if (tid == 0) {
                int cnt = 0;
                for (int i2 = 0; i2 < 1024; i2++) {
                    unsigned char kp = 0;
                    if (keys[i2] == thr) { if (cnt < r) kp = 1; cnt++; }
                    keepEq[i2] = kp;
                }
            }
            __syncthreads();
        }
    }

    float lmax = -3.402823466e38f;
#pragma unroll
    for (int i = 0; i < 4; i++) lmax = fmaxf(lmax, vals[tid + (i << 8)]);
    red[tid] = lmax;
    __syncthreads();
    for (int s = 128; s > 0; s >>= 1) {
        if (tid < s) red[tid] = fmaxf(red[tid], red[tid + s]);
        __syncthreads();
    }
    const float m = red[0];
    __syncthreads();

    float ev[4];
    float lsum = 0.f;
#pragma unroll
    for (int i = 0; i < 4; i++) {
        int idx = tid + (i << 8);
        unsigned kk = keys[idx];
        bool keep = dense || (kk > thr) || (kk == thr && (!tie || keepEq[idx]));
        float e = keep ? expf(vals[idx] - m) : 0.f;
        ev[i] = e;
        lsum += e;
    }
    red[tid] = lsum;
    __syncthreads();
    for (int s = 128; s > 0; s >>= 1) {
        if (tid < s) red[tid] += red[tid + s];
        __syncthreads();
    }
    const float inv = 1.f / red[0];
#pragma unroll
    for (int i = 0; i < 4; i++) a[tid + (i << 8)] = ev[i] * inv;
}

// ---------------------------------------------------------------------------
extern "C" void kernel_launch(void* const* d_in, const int* in_sizes, int n_in,
                              void* d_out, int out_size)
{
    const float* q     = (const float*)d_in[0];
    const float* k     = (const float*)d_in[1];
    const float* v     = (const float*)d_in[2];
    const float* qmask = (const float*)d_in[3];
    const float* w_qs  = (const float*)d_in[4];
    const float* w_ks  = (const float*)d_in[5];
    const float* w_vs  = (const float*)d_in[6];
    const float* fc_w  = (const float*)d_in[7];
    float* outP = (float*)d_out;

    float *qp, *kp, *vp, *mix, *attnScratch;
    cudaGetSymbolAddress((void**)&qp,  g_qp);
    cudaGetSymbolAddress((void**)&kp,  g_kp);
    cudaGetSymbolAddress((void**)&vp,  g_vp);
    cudaGetSymbolAddress((void**)&mix, g_mix);
    cudaGetSymbolAddress((void**)&attnScratch, g_attn);

    const long long outElems  = 8LL * 1024 * 768;
    const long long attnElems = 8LL * 4 * 1024 * 1024;
    float* attnP = ((long long)out_size >= outElems + attnElems) ? (outP + outElems)
                                                                 : attnScratch;

    const float scaleDiv = 45.254834f;  // float32(sqrt(2048)), matches jnp q_proj/scale

    // q_proj: sequential ascending-e chain, then IEEE-divide by sqrt(DK)
    gemm_nt<<<dim3(64, 64, 1), dim3(256)>>>(q, w_qs, qp, 896, 896, 896, 8192,
                                            1, 0, 0, 0, 0, 0, 0, 1.f, scaleDiv);
    // k_proj
    gemm_nt<<<dim3(64, 64, 1), dim3(256)>>>(k, w_ks, kp, 896, 896, 896, 8192,
                                            1, 0, 0, 0, 0, 0, 0, 1.f, 1.f);
    // v_proj
    gemm_nt<<<dim3(24, 64, 1), dim3(256)>>>(v, w_vs, vp, 768, 768, 768, 3072,
                                            1, 0, 0, 0, 0, 0, 0, 1.f, 1.f);

    // attn scores: per (b,h) [1024,1024] = (Q/sqrt(DK)) @ K^T, sequential chain
    gemm_nt<<<dim3(8, 8, 32), dim3(256)>>>(qp, kp, attnP, 2048, 8192, 8192, 1024,
                                           4,
                                           1024LL * 8192, 2048,
                                           1024LL * 8192, 2048,
                                           4LL * 1024 * 1024, 1024LL * 1024,
                                           1.f, 1.f);

    // exact top-64 + softmax, in place
    topk_softmax_kernel<<<32768, 256>>>(attnP, qmask);

    // mixed: per (b,h) [1024,768] = attn @ Vproj ; stored as [B, L, H, DV]
    gemm_nn<<<dim3(6, 8, 32), dim3(256)>>>(attnP, vp, mix, 1024, 1024, 3072, 3072,
                                           4,
                                           4LL * 1024 * 1024, 1024LL * 1024,
                                           1024LL * 3072, 768,
                                           1024LL * 3072, 768,
                                           1.f);

    // out: [8192,768] = mixed[8192,3072] @ fc_w[768,3072]^T
    gemm_nt<<<dim3(6, 64, 1), dim3(256)>>>(mix, fc_w, outP, 3072, 3072, 3072, 768,
                                           1, 0, 0, 0, 0, 0, 0, 1.f, 1.f);
}

// round 10
// speedup vs baseline: 1.1309x; 1.0896x over previous
#include <cuda_runtime.h>
#include <math.h>

// Problem constants
// B=8, L=1024, E=896, H=4, DK=2048, DV=768, TOP_K=64

__device__ float g_qp[67108864];   // 8192*8192 q_proj (pre-divided by sqrt(DK))
__device__ float g_kp[67108864];   // 8192*8192 k_proj
__device__ float g_vp[25165824];   // 8192*3072 v_proj
__device__ float g_mix[25165824];  // [B, L, H, DV] = 8192*3072
__device__ float g_attn[33554432]; // fallback attn scratch

// ---------------------------------------------------------------------------
// NT GEMM: C[M,N] = A(MxK) * B(NxK)^T, 128x128 tile, BK=16, 256 thr, 8x8/thr.
// Double-buffered smem + register prefetch; ONE __syncthreads per iteration.
// B fragments split as [tx*4, tx*4+64): 16B lane stride -> conflict-free LDS
// (the old tx*8 mapping had a 4-way bank conflict on every B load).
// Per-output accumulation remains a SINGLE sequential ascending-k fma chain
// (bit-identical to the reference; the top-k keep-set depends on it).
// Epilogue: divisor!=1 -> C = __fdiv_rn(acc, divisor), else C = alpha*acc.
// ---------------------------------------------------------------------------
__global__ __launch_bounds__(256, 2) void gemm_nt(
    const float* __restrict__ A, const float* __restrict__ B, float* __restrict__ C,
    int K, int lda, int ldb, int ldc, int hdiv,
    long long sa1, long long sa2, long long sb1, long long sb2,
    long long sc1, long long sc2, float alpha, float divisor)
{
    __shared__ float As[2][16][128];
    __shared__ float Bs[2][16][128];

    const int z = blockIdx.z;
    const long long zb = z / hdiv, zh = z % hdiv;
    A += zb * sa1 + zh * sa2;
    B += zb * sb1 + zh * sb2;
    C += zb * sc1 + zh * sc2;

    const int tid = threadIdx.x;
    const long long bm = (long long)blockIdx.y * 128;
    const long long bn = (long long)blockIdx.x * 128;

    const int lr = tid >> 2;          // 0..63
    const int lk = (tid & 3) << 2;    // 0,4,8,12
    const int ty = tid >> 4;          // 0..15 (8-row group)
    const int tx = tid & 15;          // 0..15 (two 4-col groups: tx*4, tx*4+64)

    float acc[8][8];
#pragma unroll
    for (int i = 0; i < 8; i++)
#pragma unroll
        for (int j = 0; j < 8; j++) acc[i][j] = 0.f;

    const float* Ap0 = A + (bm + lr) * lda + lk;
    const float* Ap1 = A + (bm + lr + 64) * lda + lk;
    const float* Bp0 = B + (bn + lr) * ldb + lk;
    const float* Bp1 = B + (bn + lr + 64) * ldb + lk;

    // prologue: load block 0 into buffer 0
    {
        float4 a0 = *(const float4*)(Ap0);
        float4 a1 = *(const float4*)(Ap1);
        float4 b0 = *(const float4*)(Bp0);
        float4 b1 = *(const float4*)(Bp1);
        As[0][lk + 0][lr] = a0.x; As[0][lk + 1][lr] = a0.y; As[0][lk + 2][lr] = a0.z; As[0][lk + 3][lr] = a0.w;
        As[0][lk + 0][lr + 64] = a1.x; As[0][lk + 1][lr + 64] = a1.y; As[0][lk + 2][lr + 64] = a1.z; As[0][lk + 3][lr + 64] = a1.w;
        Bs[0][lk + 0][lr] = b0.x; Bs[0][lk + 1][lr] = b0.y; Bs[0][lk + 2][lr] = b0.z; Bs[0][lk + 3][lr] = b0.w;
        Bs[0][lk + 0][lr + 64] = b1.x; Bs[0][lk + 1][lr + 64] = b1.y; Bs[0][lk + 2][lr + 64] = b1.z; Bs[0][lk + 3][lr + 64] = b1.w;
    }
    __syncthreads();

    int buf = 0;
    for (int k0 = 0; k0 < K; k0 += 16) {
        const bool has_next = (k0 + 16 < K);
        float4 na0, na1, nb0, nb1;
        if (has_next) {
            na0 = *(const float4*)(Ap0 + k0 + 16);
            na1 = *(const float4*)(Ap1 + k0 + 16);
            nb0 = *(const float4*)(Bp0 + k0 + 16);
            nb1 = *(const float4*)(Bp1 + k0 + 16);
        }

#pragma unroll
        for (int kk = 0; kk < 16; kk++) {
            float4 t0 = *(const float4*)(&As[buf][kk][ty * 8]);
            float4 t1 = *(const float4*)(&As[buf][kk][ty * 8 + 4]);
            float4 u0 = *(const float4*)(&Bs[buf][kk][tx * 4]);
            float4 u1 = *(const float4*)(&Bs[buf][kk][tx * 4 + 64]);
            float av[8] = {t0.x, t0.y, t0.z, t0.w, t1.x, t1.y, t1.z, t1.w};
            float bv[8] = {u0.x, u0.y, u0.z, u0.w, u1.x, u1.y, u1.z, u1.w};
#pragma unroll
            for (int i = 0; i < 8; i++)
#pragma unroll
                for (int j = 0; j < 8; j++)
                    acc[i][j] = fmaf(av[i], bv[j], acc[i][j]);
        }

        if (has_next) {
            const int nb = buf ^ 1;
            As[nb][lk + 0][lr] = na0.x; As[nb][lk + 1][lr] = na0.y; As[nb][lk + 2][lr] = na0.z; As[nb][lk + 3][lr] = na0.w;
            As[nb][lk + 0][lr + 64] = na1.x; As[nb][lk + 1][lr + 64] = na1.y; As[nb][lk + 2][lr + 64] = na1.z; As[nb][lk + 3][lr + 64] = na1.w;
            Bs[nb][lk + 0][lr] = nb0.x; Bs[nb][lk + 1][lr] = nb0.y; Bs[nb][lk + 2][lr] = nb0.z; Bs[nb][lk + 3][lr] = nb0.w;
            Bs[nb][lk + 0][lr + 64] = nb1.x; Bs[nb][lk + 1][lr + 64] = nb1.y; Bs[nb][lk + 2][lr + 64] = nb1.z; Bs[nb][lk + 3][lr + 64] = nb1.w;
        }
        __syncthreads();
        buf ^= 1;
    }

    const bool dodiv = (divisor != 1.0f);
#pragma unroll
    for (int i = 0; i < 8; i++) {
        float* Cr = C + (bm + ty * 8 + i) * ldc + bn;
        float o[8];
#pragma unroll
        for (int j = 0; j < 8; j++)
            o[j] = dodiv ? __fdiv_rn(acc[i][j], divisor) : alpha * acc[i][j];
        *(float4*)(Cr + tx * 4)      = make_float4(o[0], o[1], o[2], o[3]);
        *(float4*)(Cr + tx * 4 + 64) = make_float4(o[4], o[5], o[6], o[7]);
    }
}

// ---------------------------------------------------------------------------
// NN GEMM: C[M,N] = A(MxK) * B(KxN)  (attn @ Vproj) — same pipelined scheme,
// same conflict-free B fragment split.
// ---------------------------------------------------------------------------
__global__ __launch_bounds__(256, 2) void gemm_nn(
    const float* __restrict__ A, const float* __restrict__ B, float* __restrict__ C,
    int K, int lda, int ldb, int ldc, int hdiv,
    long long sa1, long long sa2, long long sb1, long long sb2,
    long long sc1, long long sc2, float alpha)
{
    __shared__ float As[2][16][128];
    __shared__ float Bs[2][16][128];

    const int z = blockIdx.z;
    const long long zb = z / hdiv, zh = z % hdiv;
    A += zb * sa1 + zh * sa2;
    B += zb * sb1 + zh * sb2;
    C += zb * sc1 + zh * sc2;

    const int tid = threadIdx.x;
    const long long bm = (long long)blockIdx.y * 128;
    const long long bn = (long long)blockIdx.x * 128;

    const int lr = tid >> 2;
    const int lk = (tid & 3) << 2;
    const int bkr = tid >> 5;         // 0..7
    const int bn4 = (tid & 31) << 2;  // 0..124
    const int ty = tid >> 4;
    const int tx = tid & 15;

    float acc[8][8];
#pragma unroll
    for (int i = 0; i < 8; i++)
#pragma unroll
        for (int j = 0; j < 8; j++) acc[i][j] = 0.f;

    const float* Ap0 = A + (bm + lr) * lda + lk;
    const float* Ap1 = A + (bm + lr + 64) * lda + lk;
    const float* Bp0 = B + (long long)bkr * ldb + bn + bn4;
    const float* Bp1 = B + (long long)(bkr + 8) * ldb + bn + bn4;

    {
        float4 a0 = *(const float4*)(Ap0);
        float4 a1 = *(const float4*)(Ap1);
        float4 b0 = *(const float4*)(Bp0);
        float4 b1 = *(const float4*)(Bp1);
        As[0][lk + 0][lr] = a0.x; As[0][lk + 1][lr] = a0.y; As[0][lk + 2][lr] = a0.z; As[0][lk + 3][lr] = a0.w;
        As[0][lk + 0][lr + 64] = a1.x; As[0][lk + 1][lr + 64] = a1.y; As[0][lk + 2][lr + 64] = a1.z; As[0][lk + 3][lr + 64] = a1.w;
        *(float4*)(&Bs[0][bkr][bn4]) = b0;
        *(float4*)(&Bs[0][bkr + 8][bn4]) = b1;
    }
    __syncthreads();

    int buf = 0;
    for (int k0 = 0; k0 < K; k0 += 16) {
        const bool has_next = (k0 + 16 < K);
        float4 na0, na1, nb0, nb1;
        if (has_next) {
            na0 = *(const float4*)(Ap0 + k0 + 16);
            na1 = *(const float4*)(Ap1 + k0 + 16);
            nb0 = *(const float4*)(Bp0 + (long long)(k0 + 16) * ldb);
            nb1 = *(const float4*)(Bp1 + (long long)(k0 + 16) * ldb);
        }

#pragma unroll
        for (int kk = 0; kk < 16; kk++) {
            float4 t0 = *(const float4*)(&As[buf][kk][ty * 8]);
            float4 t1 = *(const float4*)(&As[buf][kk][ty * 8 + 4]);
            float4 u0 = *(const float4*)(&Bs[buf][kk][tx * 4]);
            float4 u1 = *(const float4*)(&Bs[buf][kk][tx * 4 + 64]);
            float av[8] = {t0.x, t0.y, t0.z, t0.w, t1.x, t1.y, t1.z, t1.w};
            float bv[8] = {u0.x, u0.y, u0.z, u0.w, u1.x, u1.y, u1.z, u1.w};
#pragma unroll
            for (int i = 0; i < 8; i++)
#pragma unroll
                for (int j = 0; j < 8; j++)
                    acc[i][j] = fmaf(av[i], bv[j], acc[i][j]);
        }

        if (has_next) {
            const int nb = buf ^ 1;
            As[nb][lk + 0][lr] = na0.x; As[nb][lk + 1][lr] = na0.y; As[nb][lk + 2][lr] = na0.z; As[nb][lk + 3][lr] = na0.w;
            As[nb][lk + 0][lr + 64] = na1.x; As[nb][lk + 1][lr + 64] = na1.y; As[nb][lk + 2][lr + 64] = na1.z; As[nb][lk + 3][lr + 64] = na1.w;
            *(float4*)(&Bs[nb][bkr][bn4]) = nb0;
            *(float4*)(&Bs[nb][bkr + 8][bn4]) = nb1;
        }
        __syncthreads();
        buf ^= 1;
    }

#pragma unroll
    for (int i = 0; i < 8; i++) {
        float* Cr = C + (bm + ty * 8 + i) * ldc + bn;
        float4 c0 = make_float4(alpha * acc[i][0], alpha * acc[i][1], alpha * acc[i][2], alpha * acc[i][3]);
        float4 c1 = make_float4(alpha * acc[i][4], alpha * acc[i][5], alpha * acc[i][6], alpha * acc[i][7]);
        *(float4*)(Cr + tx * 4)      = c0;
        *(float4*)(Cr + tx * 4 + 64) = c1;
    }
}

// ---------------------------------------------------------------------------
// Exact top-64 (torch/jax topk semantics incl. first-index tie break) + softmax
// ---------------------------------------------------------------------------
__global__ __launch_bounds__(256) void topk_softmax_kernel(
    float* __restrict__ attn, const float* __restrict__ qmask)
{
    __shared__ unsigned keys[1024];
    __shared__ float vals[1024];
    __shared__ unsigned hist[256];
    __shared__ float red[256];
    __shared__ unsigned char keepEq[1024];
    __shared__ unsigned sh_prefix, sh_krem, sh_e;

    const int tid = threadIdx.x;
    const int row = blockIdx.x;             // (b*H + h)*L + lq
    float* a = attn + (long long)row * 1024;
    const int b = row >> 12;                // H*L = 4096
    const int lq = row & 1023;
    const float mk = qmask[(b << 10) + lq];
    const bool dense = (mk <= 0.5f);

#pragma unroll
    for (int i = 0; i < 4; i++) {
        int idx = tid + (i << 8);
        float x = a[idx];
        vals[idx] = x;
        unsigned u = __float_as_uint(x);
        keys[idx] = (u & 0x80000000u) ? ~u : (u | 0x80000000u);
    }
    __syncthreads();

    unsigned thr = 0;
    int r = 0;
    bool tie = false;
    if (!dense) {
        unsigned prefix = 0;
        int krem = 64;
        for (int pass = 0; pass < 4; pass++) {
            const int shift = 24 - (pass << 3);
            hist[tid] = 0;
            __syncthreads();
            const unsigned pmask = (pass == 0) ? 0u : (0xFFFFFFFFu << (shift + 8));
#pragma unroll
            for (int i = 0; i < 4; i++) {
                unsigned kk = keys[tid + (i << 8)];
                if ((kk & pmask) == prefix)
                    atomicAdd(&hist[(kk >> shift) & 255u], 1u);
            }
            __syncthreads();
            if (tid == 0) {
                int cum = 0, bsel = 0;
                for (int bb = 255; bb >= 0; bb--) {
                    int c = (int)hist[bb];
                    if (cum + c >= krem) { bsel = bb; break; }
                    cum += c;
                }
                sh_prefix = prefix | ((unsigned)bsel << shift);
                sh_krem = (unsigned)(krem - cum);
            }
            __syncthreads();
            prefix = sh_prefix;
            krem = (int)sh_krem;
        }
        thr = prefix;
        r = krem;
        if (tid == 0) sh_e = 0;
        __syncthreads();
        unsigned le = 0;
#pragma unroll
        for (int i = 0; i < 4; i++) le += (keys[tid + (i << 8)] == thr) ? 1u : 0u;
        if (le) atomicAdd(&sh_e, le);
        __syncthreads();
        tie = ((int)sh_e != r);
        if (tie) {
            if (tid == 0) {
                int cnt = 0;
                for (int i2 = 0; i2 < 1024; i2++) {
                    unsigned char kp = 0;
                    if (keys[i2] == thr) { if (cnt < r) kp = 1; cnt++; }
                    keepEq[i2] = kp;
                }
            }
            __syncthreads();
        }
    }

    float lmax = -3.402823466e38f;
#pragma unroll
    for (int i = 0; i < 4; i++) lmax = fmaxf(lmax, vals[tid + (i << 8)]);
    red[tid] = lmax;
    __syncthreads();
    for (int s = 128; s > 0; s >>= 1) {
        if (tid < s) red[tid] = fmaxf(red[tid], red[tid + s]);
        __syncthreads();
    }
    const float m = red[0];
    __syncthreads();

    float ev[4];
    float lsum = 0.f;
#pragma unroll
    for (int i = 0; i < 4; i++) {
        int idx = tid + (i << 8);
        unsigned kk = keys[idx];
        bool keep = dense || (kk > thr) || (kk == thr && (!tie || keepEq[idx]));
        float e = keep ? expf(vals[idx] - m) : 0.f;
        ev[i] = e;
        lsum += e;
    }
    red[tid] = lsum;
    __syncthreads();
    for (int s = 128; s > 0; s >>= 1) {
        if (tid < s) red[tid] += red[tid + s];
        __syncthreads();
    }
    const float inv = 1.f / red[0];
#pragma unroll
    for (int i = 0; i < 4; i++) a[tid + (i << 8)] = ev[i] * inv;
}

// ---------------------------------------------------------------------------
extern "C" void kernel_launch(void* const* d_in, const int* in_sizes, int n_in,
                              void* d_out, int out_size)
{
    const float* q     = (const float*)d_in[0];
    const float* k     = (const float*)d_in[1];
    const float* v     = (const float*)d_in[2];
    const float* qmask = (const float*)d_in[3];
    const float* w_qs  = (const float*)d_in[4];
    const float* w_ks  = (const float*)d_in[5];
    const float* w_vs  = (const float*)d_in[6];
    const float* fc_w  = (const float*)d_in[7];
    float* outP = (float*)d_out;

    float *qp, *kp, *vp, *mix, *attnScratch;
    cudaGetSymbolAddress((void**)&qp,  g_qp);
    cudaGetSymbolAddress((void**)&kp,  g_kp);
    cudaGetSymbolAddress((void**)&vp,  g_vp);
    cudaGetSymbolAddress((void**)&mix, g_mix);
    cudaGetSymbolAddress((void**)&attnScratch, g_attn);

    const long long outElems  = 8LL * 1024 * 768;
    const long long attnElems = 8LL * 4 * 1024 * 1024;
    float* attnP = ((long long)out_size >= outElems + attnElems) ? (outP + outElems)
                                                                 : attnScratch;

    const float scaleDiv = 45.254834f;  // float32(sqrt(2048)), matches jnp q_proj/scale

    // q_proj: sequential ascending-e chain, then IEEE-divide by sqrt(DK)
    gemm_nt<<<dim3(64, 64, 1), dim3(256)>>>(q, w_qs, qp, 896, 896, 896, 8192,
                                            1, 0, 0, 0, 0, 0, 0, 1.f, scaleDiv);
    // k_proj
    gemm_nt<<<dim3(64, 64, 1), dim3(256)>>>(k, w_ks, kp, 896, 896, 896, 8192,
                                            1, 0, 0, 0, 0, 0, 0, 1.f, 1.f);
    // v_proj
    gemm_nt<<<dim3(24, 64, 1), dim3(256)>>>(v, w_vs, vp, 768, 768, 768, 3072,
                                            1, 0, 0, 0, 0, 0, 0, 1.f, 1.f);

    // attn scores: per (b,h) [1024,1024] = (Q/sqrt(DK)) @ K^T, sequential chain
    gemm_nt<<<dim3(8, 8, 32), dim3(256)>>>(qp, kp, attnP, 2048, 8192, 8192, 1024,
                                           4,
                                           1024LL * 8192, 2048,
                                           1024LL * 8192, 2048,
                                           4LL * 1024 * 1024, 1024LL * 1024,
                                           1.f, 1.f);

    // exact top-64 + softmax, in place
    topk_softmax_kernel<<<32768, 256>>>(attnP, qmask);

    // mixed: per (b,h) [1024,768] = attn @ Vproj ; stored as [B, L, H, DV]
    gemm_nn<<<dim3(6, 8, 32), dim3(256)>>>(attnP, vp, mix, 1024, 1024, 3072, 3072,
                                           4,
                                           4LL * 1024 * 1024, 1024LL * 1024,
                                           1024LL * 3072, 768,
                                           1024LL * 3072, 768,
                                           1.f);

    // out: [8192,768] = mixed[8192,3072] @ fc_w[768,3072]^T
    gemm_nt<<<dim3(6, 64, 1), dim3(256)>>>(mix, fc_w, outP, 3072, 3072, 3072, 768,
                                           1, 0, 0, 0, 0, 0, 0, 1.f, 1.f);
}